// round 11
// baseline (speedup 1.0000x reference)
#include <cuda_runtime.h>
#include <cuda_fp16.h>

// Problem constants
#define B_DIM 8
#define C_DIM 64
#define T_DIM 128
#define N_DIM 207
#define TN    (T_DIM * N_DIM)
#define L2E   1.4426950408889634f

// Fused tiling
#define NS     20            // n per block
#define TT     16            // output t per block
#define PT     22            // TT + 6 halo
#define PIXKV  (PT * NS)     // 440 K/V pixel rows
#define MROWS  448           // 28 m16 tiles (padded)
#define MTILES 28
#define STRH   70            // half stride of QKV smem rows [pix][o]
#define NTILES 11            // ceil(207/20)
#define NTHREADS 512

// Dynamic SMEM layout (bytes)
#define SO_BIAS 0
#define SO_W    256                          // 64*72 halves = 9216 B
#define SO_AS   (SO_W + 64 * 72 * 2)         // 448*24 halves = 21504 B
#define SO_Q    (SO_AS + MROWS * 24 * 2)     // 320*70 halves = 44800 B
#define SO_K    (SO_Q + TT * NS * STRH * 2)  // 440*70 halves = 61600 B
#define SO_V    (SO_K + PIXKV * STRH * 2)
#define SMEM_TOTAL (SO_V + PIXKV * STRH * 2) // 198976 B

__device__ __forceinline__ void mma_fp16(float* d, const unsigned* a, const unsigned* b) {
    asm volatile(
        "mma.sync.aligned.m16n8k16.row.col.f32.f16.f16.f32 "
        "{%0,%1,%2,%3},{%4,%5,%6,%7},{%8,%9},{%0,%1,%2,%3};\n"
        : "+f"(d[0]), "+f"(d[1]), "+f"(d[2]), "+f"(d[3])
        : "r"(a[0]), "r"(a[1]), "r"(a[2]), "r"(a[3]),
          "r"(b[0]), "r"(b[1]));
}

__device__ __forceinline__ float ex2f(float x) {
    float y;
    asm("ex2.approx.f32 %0, %1;" : "=f"(y) : "f"(x));
    return y;
}

// As half-index: row-major stride 24, XOR swizzle on c bits [1:2] keyed by
// pix bits [3:4]. Conflict-free for pix-consecutive STS.16 AND for m16n8k16
// A-fragment LDS.32 (bank bases {0,12,24,4,16,28,8,20} are the 8 multiples
// of 4; XOR offsets fill each 4-block -> 32 lanes, 32 banks).
__device__ __forceinline__ int as_idx(int pix, int cl) {
    return pix * 24 + (cl ^ (((pix >> 3) & 3) << 1));
}

__global__ __launch_bounds__(NTHREADS, 1) void fused_kernel(
    float* __restrict__ out,
    const float* __restrict__ q, const float* __restrict__ k, const float* __restrict__ v,
    const float* __restrict__ Wq, const float* __restrict__ bq,
    const float* __restrict__ Wk, const float* __restrict__ bk,
    const float* __restrict__ Wv, const float* __restrict__ bv)
{
    extern __shared__ __align__(16) char sm[];
    float*  bias_s = (float*)(sm + SO_BIAS);
    __half* Wsm    = (__half*)(sm + SO_W);
    __half* As     = (__half*)(sm + SO_AS);
    __half* Qs     = (__half*)(sm + SO_Q);
    __half* Ks     = (__half*)(sm + SO_K);
    __half* Vs     = (__half*)(sm + SO_V);

    const int tid = threadIdx.x;
    const int n0  = blockIdx.x * NS;
    const int t0  = blockIdx.y * TT;
    const int b   = blockIdx.z;

    // Per-thread staging pixel (pix = tid for tid < MROWS)
    const int sp_t = tid / NS;            // t_loc 0..22 (tid<448)
    const int sp_n = tid - sp_t * NS;
    const int sg_t = t0 - 3 + sp_t;       // global t for this pixel row
    const int sg_n = n0 + sp_n;
    const bool sp_ok = (tid < MROWS) && (sg_t >= 0) && (sg_t < T_DIM) && (sg_n < N_DIM);
    // Clamped (always in-bounds) base address: (((b*64 + c)*128 + t)*207 + n)
    const int tcl = (sg_t < 0) ? 0 : ((sg_t > 127) ? 127 : sg_t);
    const int ncl = (sg_n > 206) ? 206 : sg_n;
    const unsigned gbase = ((unsigned)(b * C_DIM) * T_DIM + (unsigned)tcl) * N_DIM + (unsigned)ncl;

    const int wid = tid >> 5, lane = tid & 31;
    const int lr = lane >> 2, lc = lane & 3;

    const float* Xz[3] = { q, k, v };
    const float* Wz[3] = { Wq, Wk, Wv };
    const float* bz[3] = { bq, bk, bv };

    for (int z = 0; z < 3; z++) {
        const float* __restrict__ X = Xz[z];
        const float* __restrict__ W = Wz[z];

        __syncthreads();   // prior z: Wsm/bias readers + As readers done

        // Stage W (fp16, stride 72 halves: proven conflict-free B-frag reads)
        for (int i = tid; i < 64 * 64; i += NTHREADS) {
            int o = i >> 6, c = i & 63;
            Wsm[o * 72 + c] = __float2half_rn(W[i]);
        }
        if (tid < 64) bias_s[tid] = bz[z][tid];

        float acc[2][8][4] = {};

        #pragma unroll 1
        for (int kc = 0; kc < 4; kc++) {
            __syncthreads();   // As consumed by previous chunk (and W staged, kc==0)
            // Stage As chunk: c = kc*16 + cl, transposed [pix][cl]
            if (tid < MROWS) {
                unsigned ga = gbase + (unsigned)(kc * 16) * TN;
                #pragma unroll
                for (int cl = 0; cl < 16; cl++) {
                    float x = sp_ok ? X[ga] : 0.0f;
                    As[as_idx(tid, cl)] = __float2half_rn(x);
                    ga += TN;
                }
            }
            __syncthreads();

            // B fragments for this k-chunk (shared across m-tiles)
            unsigned Bf[8][2];
            #pragma unroll
            for (int nt = 0; nt < 8; nt++) {
                int o = nt * 8 + lr;
                int c = kc * 16 + 2 * lc;
                Bf[nt][0] = *(const unsigned*)&Wsm[o * 72 + c];
                Bf[nt][1] = *(const unsigned*)&Wsm[o * 72 + c + 8];
            }
            #pragma unroll
            for (int mt = 0; mt < 2; mt++) {
                int tile = wid + 16 * mt;
                if (tile < MTILES) {
                    int r0 = tile * 16 + lr, r1 = r0 + 8;
                    int c0 = 2 * lc, c1 = 2 * lc + 8;
                    unsigned Af[4];
                    Af[0] = *(const unsigned*)&As[as_idx(r0, c0)];
                    Af[1] = *(const unsigned*)&As[as_idx(r1, c0)];
                    Af[2] = *(const unsigned*)&As[as_idx(r0, c1)];
                    Af[3] = *(const unsigned*)&As[as_idx(r1, c1)];
                    #pragma unroll
                    for (int nt = 0; nt < 8; nt++)
                        mma_fp16(acc[mt][nt], Af, Bf[nt]);
                }
            }
        }

        // Epilogue: acc + bias -> fp16 [pix][o] (stride 70 halves, half2 stores)
        const float qs = (z == 0) ? L2E : 1.0f;
        __half* Dst = (z == 1) ? Ks : Vs;   // z==0 handled separately
        #pragma unroll
        for (int mt = 0; mt < 2; mt++) {
            int tile = wid + 16 * mt;
            if (tile >= MTILES) continue;
            #pragma unroll
            for (int nt = 0; nt < 8; nt++) {
                int ob = nt * 8 + 2 * lc;
                float b0 = bias_s[ob], b1 = bias_s[ob + 1];
                #pragma unroll
                for (int h = 0; h < 2; h++) {
                    int row = tile * 16 + lr + h * 8;
                    if (row >= PIXKV) continue;
                    float y0 = (acc[mt][nt][2 * h + 0] + b0) * qs;
                    float y1 = (acc[mt][nt][2 * h + 1] + b1) * qs;
                    if (z == 0) {
                        // Q: keep only t_loc in [3,19) -> buffer rows 0..319
                        if (row >= 3 * NS && row < (3 + TT) * NS) {
                            *(__half2*)&Qs[(row - 3 * NS) * STRH + ob] =
                                __floats2half2_rn(y0, y1);
                        }
                    } else {
                        // K/V: zero t-pad rows (reference pads AFTER projection)
                        bool kvz = (t0 == 0 && row < 3 * NS) ||
                                   (t0 == T_DIM - TT && row >= (3 + TT) * NS);
                        if (kvz) { y0 = 0.0f; y1 = 0.0f; }
                        *(__half2*)&Dst[row * STRH + ob] = __floats2half2_rn(y0, y1);
                    }
                }
            }
        }
    }

    __syncthreads();   // QKV smem fully built

    // ---- Attention: 7-tap sliding-window softmax from SMEM ----
    // 5120 items = 64 o x 4 t-groups x 20 n; each item = 4 t-outputs sharing
    // a 10-row K/V window (6 LDS per output instead of 14).
    #pragma unroll 1
    for (int it = 0; it < 10; it++) {
        int item  = tid + NTHREADS * it;
        int n_loc = item % NS;
        int rem   = item / NS;      // 0..255
        int tg    = rem & 3;
        int o     = rem >> 2;       // 0..63
        int n     = n0 + n_loc;
        if (n >= N_DIM) continue;

        int base_pix = (tg * 4) * NS + n_loc;   // K/V row of t_out_local = tg*4, tap -3
        float kw[10], vw[10];
        #pragma unroll
        for (int r = 0; r < 10; r++) {
            int p = base_pix + r * NS;
            kw[r] = __half2float(Ks[p * STRH + o]);
            vw[r] = __half2float(Vs[p * STRH + o]);
        }

        unsigned obase = (((unsigned)b * C_DIM + (unsigned)o) * T_DIM +
                          (unsigned)(t0 + tg * 4)) * N_DIM + (unsigned)n;
        #pragma unroll
        for (int j = 0; j < 4; j++) {
            float qv = __half2float(Qs[(base_pix + j * NS) * STRH + o]);  // log2e-scaled
            float den = 0.0f, num = 0.0f;
            #pragma unroll
            for (int i = 0; i < 7; i++) {
                float e = ex2f(qv * kw[j + i]);   // pad rows: kw=0 -> e=1 (matches ref)
                den += e;
                num = fmaf(e, vw[j + i], num);
            }
            out[obase + (unsigned)(j * N_DIM)] = __fdividef(num, den);
        }
    }
}

// ---------------- launch ----------------
extern "C" void kernel_launch(void* const* d_in, const int* in_sizes, int n_in,
                              void* d_out, int out_size)
{
    (void)in_sizes; (void)n_in; (void)out_size;
    const float* q  = (const float*)d_in[0];
    const float* k  = (const float*)d_in[1];
    const float* v  = (const float*)d_in[2];
    const float* Wq = (const float*)d_in[3];
    const float* bq = (const float*)d_in[4];
    const float* Wk = (const float*)d_in[5];
    const float* bk = (const float*)d_in[6];
    const float* Wv = (const float*)d_in[7];
    const float* bv = (const float*)d_in[8];

    cudaFuncSetAttribute(fused_kernel,
                         cudaFuncAttributeMaxDynamicSharedMemorySize, SMEM_TOTAL);

    dim3 grid(NTILES, T_DIM / TT, B_DIM);
    fused_kernel<<<grid, NTHREADS, SMEM_TOTAL>>>(
        (float*)d_out, q, k, v, Wq, bq, Wk, bk, Wv, bv);
}